// round 1
// baseline (speedup 1.0000x reference)
#include <cuda_runtime.h>
#include <cuda_bf16.h>
#include <math.h>

#define N_NODES 50000
#define N_EDGES 800000
#define DIM     128
#define N_LAYERS 4
#define BN_EPS  1e-5f

// ---------------- scratch (device globals; no allocations allowed) ----------
__device__ int    g_deg[N_NODES];
__device__ int    g_rowptr[N_NODES + 1];
__device__ int    g_cursor[N_NODES];
__device__ int    g_srcs[N_EDGES];
__device__ float  g_dis[N_NODES];
__device__ float  g_h[(size_t)N_NODES * DIM];
__device__ float  g_y[(size_t)N_NODES * DIM];
__device__ float  g_z[(size_t)N_NODES * DIM];
__device__ double g_stats[2 * DIM];    // [0:128) sum, [128:256) sumsq
__device__ float  g_affine[2 * DIM];   // [0:128) scale, [128:256) shift

// ---------------- CSR build ------------------------------------------------
__global__ void count_kernel(const int* __restrict__ dst) {
    int e = blockIdx.x * blockDim.x + threadIdx.x;
    if (e < N_EDGES) atomicAdd(&g_deg[dst[e]], 1);
}

// single-block scan over 50000 degrees; also produces cursor (exclusive) and dis
__global__ void __launch_bounds__(1024) scan_kernel() {
    __shared__ int wsum[32];
    __shared__ int carry_s;
    int tid = threadIdx.x;
    int lane = tid & 31, wid = tid >> 5;
    if (tid == 0) { carry_s = 0; g_rowptr[0] = 0; }
    __syncthreads();
    for (int base = 0; base < N_NODES; base += 1024) {
        int i = base + tid;
        int v = (i < N_NODES) ? g_deg[i] : 0;
        int x = v;
        #pragma unroll
        for (int o = 1; o < 32; o <<= 1) {
            int t = __shfl_up_sync(0xffffffffu, x, o);
            if (lane >= o) x += t;
        }
        if (lane == 31) wsum[wid] = x;
        __syncthreads();
        if (wid == 0) {
            int w = wsum[lane];
            #pragma unroll
            for (int o = 1; o < 32; o <<= 1) {
                int t = __shfl_up_sync(0xffffffffu, w, o);
                if (lane >= o) w += t;
            }
            wsum[lane] = w;
        }
        __syncthreads();
        int incl = x + (wid > 0 ? wsum[wid - 1] : 0) + carry_s;
        if (i < N_NODES) {
            g_rowptr[i + 1] = incl;
            g_cursor[i]     = incl - v;
            g_dis[i]        = rsqrtf((float)v + 1.0f);
        }
        __syncthreads();
        if (tid == 1023) carry_s = incl;
        __syncthreads();
    }
}

__global__ void scatter_kernel(const int* __restrict__ src, const int* __restrict__ dst) {
    int e = blockIdx.x * blockDim.x + threadIdx.x;
    if (e < N_EDGES) {
        int d = dst[e];
        int p = atomicAdd(&g_cursor[d], 1);
        g_srcs[p] = src[e];
    }
}

// ---------------- GEMM: H = Z @ W (N x 128 @ 128 x 128, fp32 via FFMA2) -----
// block: 256 threads, 64 rows; W fully in smem; Z tile transposed in smem
#define GEMM_SMEM_BYTES ((128 * 128 + 128 * 65) * 4)

__global__ void __launch_bounds__(256) gemm_kernel(const float* __restrict__ Z,
                                                   const float* __restrict__ W,
                                                   float* __restrict__ H) {
    extern __shared__ float smem[];
    float* Wsm = smem;               // [128][128]
    float* Zsm = smem + 128 * 128;   // [128][65] (transposed, padded)

    int tid  = threadIdx.x;
    int row0 = blockIdx.x * 64;

    // load W (4096 float4 / 256 threads = 16 each)
    const float4* W4 = (const float4*)W;
    float4* Ws4 = (float4*)Wsm;
    #pragma unroll
    for (int i = 0; i < 16; i++) Ws4[tid + i * 256] = W4[tid + i * 256];

    // load Z tile transposed: thread t -> row t>>2, k-quads (t&3)+4q
    {
        int r  = tid >> 2;
        int kq = tid & 3;
        #pragma unroll
        for (int q = 0; q < 8; q++) {
            int k4   = kq + q * 4;         // float4 index along K
            int grow = row0 + r;
            float4 v = (grow < N_NODES) ? ((const float4*)Z)[(size_t)grow * 32 + k4]
                                        : make_float4(0.f, 0.f, 0.f, 0.f);
            int k = k4 * 4;
            Zsm[(k + 0) * 65 + r] = v.x;
            Zsm[(k + 1) * 65 + r] = v.y;
            Zsm[(k + 2) * 65 + r] = v.z;
            Zsm[(k + 3) * 65 + r] = v.w;
        }
    }
    __syncthreads();

    int cg = tid & 31;   // column group: cols cg*4..cg*4+3
    int rg = tid >> 5;   // row group:    rows rg*8..rg*8+7

    unsigned long long acc[8][2];
    #pragma unroll
    for (int i = 0; i < 8; i++) { acc[i][0] = 0ull; acc[i][1] = 0ull; }

    #pragma unroll 4
    for (int k = 0; k < 128; k++) {
        float4 bv = *(const float4*)&Wsm[k * 128 + cg * 4];
        unsigned long long b01, b23;
        asm("mov.b64 %0, {%1,%2};" : "=l"(b01) : "f"(bv.x), "f"(bv.y));
        asm("mov.b64 %0, {%1,%2};" : "=l"(b23) : "f"(bv.z), "f"(bv.w));
        const float* zp = &Zsm[k * 65 + rg * 8];
        #pragma unroll
        for (int i = 0; i < 8; i++) {
            float a = zp[i];
            unsigned long long aa;
            asm("mov.b64 %0, {%1,%1};" : "=l"(aa) : "f"(a));
            asm("fma.rn.f32x2 %0, %1, %2, %0;" : "+l"(acc[i][0]) : "l"(aa), "l"(b01));
            asm("fma.rn.f32x2 %0, %1, %2, %0;" : "+l"(acc[i][1]) : "l"(aa), "l"(b23));
        }
    }

    #pragma unroll
    for (int i = 0; i < 8; i++) {
        int row = row0 + rg * 8 + i;
        if (row < N_NODES) {
            float4 o;
            asm("mov.b64 {%0,%1}, %2;" : "=f"(o.x), "=f"(o.y) : "l"(acc[i][0]));
            asm("mov.b64 {%0,%1}, %2;" : "=f"(o.z), "=f"(o.w) : "l"(acc[i][1]));
            ((float4*)H)[(size_t)row * 32 + cg] = o;
        }
    }
}

// ---------------- Aggregation + bias + ReLU + BN-stat accumulation ----------
// one warp per dst row (grid-stride); lane owns cols lane*4..lane*4+3
__global__ void __launch_bounds__(256) agg_kernel(const float* __restrict__ bvec) {
    __shared__ float red[8 * 256];

    int lane = threadIdx.x & 31;
    int wid  = threadIdx.x >> 5;
    int gw   = blockIdx.x * 8 + wid;
    int nw   = gridDim.x * 8;

    float4 bb = ((const float4*)bvec)[lane];

    float s0 = 0.f, s1 = 0.f, s2 = 0.f, s3 = 0.f;
    float q0 = 0.f, q1 = 0.f, q2 = 0.f, q3 = 0.f;

    const float4* h4 = (const float4*)g_h;

    for (int r = gw; r < N_NODES; r += nw) {
        float dr = g_dis[r];
        float4 hv = h4[(size_t)r * 32 + lane];
        float cself = dr * dr;
        float4 acc;
        acc.x = hv.x * cself; acc.y = hv.y * cself;
        acc.z = hv.z * cself; acc.w = hv.w * cself;

        int beg = g_rowptr[r], end = g_rowptr[r + 1];
        for (int j = beg; j < end; j++) {
            int s = g_srcs[j];
            float c = g_dis[s] * dr;
            float4 hs = h4[(size_t)s * 32 + lane];
            acc.x = fmaf(c, hs.x, acc.x);
            acc.y = fmaf(c, hs.y, acc.y);
            acc.z = fmaf(c, hs.z, acc.z);
            acc.w = fmaf(c, hs.w, acc.w);
        }
        acc.x = fmaxf(acc.x + bb.x, 0.f);
        acc.y = fmaxf(acc.y + bb.y, 0.f);
        acc.z = fmaxf(acc.z + bb.z, 0.f);
        acc.w = fmaxf(acc.w + bb.w, 0.f);
        ((float4*)g_y)[(size_t)r * 32 + lane] = acc;

        s0 += acc.x; s1 += acc.y; s2 += acc.z; s3 += acc.w;
        q0 = fmaf(acc.x, acc.x, q0); q1 = fmaf(acc.y, acc.y, q1);
        q2 = fmaf(acc.z, acc.z, q2); q3 = fmaf(acc.w, acc.w, q3);
    }

    // per-warp stash: red[wid*256 + lane*8 + j]; j 0..3 sums, 4..7 sumsq
    float* rw = &red[wid * 256 + lane * 8];
    rw[0] = s0; rw[1] = s1; rw[2] = s2; rw[3] = s3;
    rw[4] = q0; rw[5] = q1; rw[6] = q2; rw[7] = q3;
    __syncthreads();

    int tid = threadIdx.x;
    float a = 0.f;
    #pragma unroll
    for (int w = 0; w < 8; w++) a += red[w * 256 + tid];
    int l = tid >> 3, j = tid & 7;
    int col = l * 4 + (j & 3);
    atomicAdd(&g_stats[(j >> 2) * 128 + col], (double)a);
}

// ---------------- BN finalize ------------------------------------------------
__global__ void stats_kernel(const float* __restrict__ gamma,
                             const float* __restrict__ beta) {
    int c = threadIdx.x;
    double mu  = g_stats[c] * (1.0 / N_NODES);
    double var = g_stats[128 + c] * (1.0 / N_NODES) - mu * mu;
    float scale = gamma[c] * rsqrtf((float)var + BN_EPS);
    g_affine[c]       = scale;
    g_affine[128 + c] = beta[c] - (float)mu * scale;
}

// ---------------- normalize (elementwise affine) -----------------------------
__global__ void __launch_bounds__(256) norm_kernel(float* __restrict__ out) {
    int idx = blockIdx.x * blockDim.x + threadIdx.x;  // float4 index
    if (idx < N_NODES * 32) {
        int c4 = idx & 31;
        float4 v  = ((const float4*)g_y)[idx];
        float4 sc = ((const float4*)g_affine)[c4];
        float4 sh = ((const float4*)(g_affine + 128))[c4];
        v.x = fmaf(v.x, sc.x, sh.x);
        v.y = fmaf(v.y, sc.y, sh.y);
        v.z = fmaf(v.z, sc.z, sh.z);
        v.w = fmaf(v.w, sc.w, sh.w);
        ((float4*)out)[idx] = v;
    }
}

// ---------------- launch -----------------------------------------------------
extern "C" void kernel_launch(void* const* d_in, const int* in_sizes, int n_in,
                              void* d_out, int out_size) {
    const float* x      = (const float*)d_in[0];
    const int*   ei     = (const int*)d_in[1];
    const float* Ws     = (const float*)d_in[2];
    const float* bs     = (const float*)d_in[3];
    const float* gammas = (const float*)d_in[4];
    const float* betas  = (const float*)d_in[5];
    const int* src = ei;
    const int* dst = ei + N_EDGES;

    void *p_deg, *p_stats, *p_z, *p_h;
    cudaGetSymbolAddress(&p_deg,   g_deg);
    cudaGetSymbolAddress(&p_stats, g_stats);
    cudaGetSymbolAddress(&p_z,     g_z);
    cudaGetSymbolAddress(&p_h,     g_h);

    cudaFuncSetAttribute(gemm_kernel, cudaFuncAttributeMaxDynamicSharedMemorySize,
                         GEMM_SMEM_BYTES);

    // CSR build (edge structure is layer-invariant)
    cudaMemsetAsync(p_deg, 0, N_NODES * sizeof(int), 0);
    count_kernel<<<(N_EDGES + 255) / 256, 256>>>(dst);
    scan_kernel<<<1, 1024>>>();
    scatter_kernel<<<(N_EDGES + 255) / 256, 256>>>(src, dst);

    const float* zin = x;
    for (int l = 0; l < N_LAYERS; l++) {
        gemm_kernel<<<(N_NODES + 63) / 64, 256, GEMM_SMEM_BYTES>>>(
            zin, Ws + (size_t)l * DIM * DIM, (float*)p_h);
        cudaMemsetAsync(p_stats, 0, 2 * DIM * sizeof(double), 0);
        agg_kernel<<<512, 256>>>(bs + l * DIM);
        stats_kernel<<<1, 128>>>(gammas + l * DIM, betas + l * DIM);
        float* zout = (l == N_LAYERS - 1) ? (float*)d_out : (float*)p_z;
        norm_kernel<<<(N_NODES * 32 + 255) / 256, 256>>>(zout);
        zin = zout;
    }
}

// round 2
// speedup vs baseline: 1.0913x; 1.0913x over previous
#include <cuda_runtime.h>
#include <cuda_bf16.h>
#include <math.h>

#define N_NODES 50000
#define N_EDGES 800000
#define DIM     128
#define N_LAYERS 4
#define BN_EPS  1e-5f

// ---------------- scratch (device globals; no allocations allowed) ----------
__device__ int    g_deg[N_NODES];
__device__ int    g_rowptr[N_NODES + 1];
__device__ int    g_cursor[N_NODES];
__device__ int2   g_edge[N_EDGES];     // (src, coef bits) in CSR order
__device__ float  g_dis[N_NODES];
__device__ float  g_h[(size_t)N_NODES * DIM];
__device__ float  g_y[(size_t)N_NODES * DIM];
__device__ double g_stats[2 * DIM];    // [0:128) sum, [128:256) sumsq  (self-zeroing)
__device__ float  g_affine[2 * DIM];   // [0:128) scale, [128:256) shift

// ---------------- CSR build ------------------------------------------------
__global__ void count_kernel(const int* __restrict__ dst) {
    int e = blockIdx.x * blockDim.x + threadIdx.x;
    if (e < N_EDGES) atomicAdd(&g_deg[dst[e]], 1);
}

// single-block scan over 50000 degrees; produces rowptr, cursor, dis; zeroes g_deg
__global__ void __launch_bounds__(1024) scan_kernel() {
    __shared__ int wsum[32];
    __shared__ int carry_s;
    int tid = threadIdx.x;
    int lane = tid & 31, wid = tid >> 5;
    if (tid == 0) { carry_s = 0; g_rowptr[0] = 0; }
    __syncthreads();
    for (int base = 0; base < N_NODES; base += 1024) {
        int i = base + tid;
        int v = (i < N_NODES) ? g_deg[i] : 0;
        int x = v;
        #pragma unroll
        for (int o = 1; o < 32; o <<= 1) {
            int t = __shfl_up_sync(0xffffffffu, x, o);
            if (lane >= o) x += t;
        }
        if (lane == 31) wsum[wid] = x;
        __syncthreads();
        if (wid == 0) {
            int w = wsum[lane];
            #pragma unroll
            for (int o = 1; o < 32; o <<= 1) {
                int t = __shfl_up_sync(0xffffffffu, w, o);
                if (lane >= o) w += t;
            }
            wsum[lane] = w;
        }
        __syncthreads();
        int incl = x + (wid > 0 ? wsum[wid - 1] : 0) + carry_s;
        if (i < N_NODES) {
            g_rowptr[i + 1] = incl;
            g_cursor[i]     = incl - v;
            g_dis[i]        = rsqrtf((float)v + 1.0f);
            g_deg[i]        = 0;   // self-zero for next call
        }
        __syncthreads();
        if (tid == 1023) carry_s = incl;
        __syncthreads();
    }
}

__global__ void scatter_kernel(const int* __restrict__ src, const int* __restrict__ dst) {
    int e = blockIdx.x * blockDim.x + threadIdx.x;
    if (e < N_EDGES) {
        int d = dst[e];
        int s = src[e];
        int p = atomicAdd(&g_cursor[d], 1);
        float c = g_dis[s] * g_dis[d];
        g_edge[p] = make_int2(s, __float_as_int(c));
    }
}

// ---------------- GEMM: H = affine(Z) @ W  (fp32 via FFMA2) ------------------
// block: 256 threads, 64 rows; W fully in smem; Z tile transposed (stride 68)
#define ZPAD 68
#define GEMM_SMEM_BYTES ((128 * 128 + 128 * ZPAD) * 4)

__global__ void __launch_bounds__(256) gemm_kernel(const float* __restrict__ Z,
                                                   const float* __restrict__ W,
                                                   float* __restrict__ H,
                                                   int apply_affine) {
    extern __shared__ float smem[];
    float* Wsm = smem;               // [128][128]
    float* Zsm = smem + 128 * 128;   // [128][ZPAD] transposed

    int tid  = threadIdx.x;
    int row0 = blockIdx.x * 64;

    // load W (4096 float4 / 256 threads = 16 each)
    const float4* W4 = (const float4*)W;
    float4* Ws4 = (float4*)Wsm;
    #pragma unroll
    for (int i = 0; i < 16; i++) Ws4[tid + i * 256] = W4[tid + i * 256];

    // load Z tile transposed (optionally applying BN affine per column)
    {
        int r  = tid >> 2;
        int kq = tid & 3;
        #pragma unroll
        for (int q = 0; q < 8; q++) {
            int k4   = kq + q * 4;
            int grow = row0 + r;
            float4 v = (grow < N_NODES) ? ((const float4*)Z)[(size_t)grow * 32 + k4]
                                        : make_float4(0.f, 0.f, 0.f, 0.f);
            if (apply_affine) {
                float4 sc = ((const float4*)g_affine)[k4];
                float4 sh = ((const float4*)g_affine)[32 + k4];
                v.x = fmaf(v.x, sc.x, sh.x);
                v.y = fmaf(v.y, sc.y, sh.y);
                v.z = fmaf(v.z, sc.z, sh.z);
                v.w = fmaf(v.w, sc.w, sh.w);
            }
            int k = k4 * 4;
            Zsm[(k + 0) * ZPAD + r] = v.x;
            Zsm[(k + 1) * ZPAD + r] = v.y;
            Zsm[(k + 2) * ZPAD + r] = v.z;
            Zsm[(k + 3) * ZPAD + r] = v.w;
        }
    }
    __syncthreads();

    int cg = tid & 31;   // column group: cols cg*4..cg*4+3
    int rg = tid >> 5;   // row group:    rows rg*8..rg*8+7

    unsigned long long acc[8][2];
    #pragma unroll
    for (int i = 0; i < 8; i++) { acc[i][0] = 0ull; acc[i][1] = 0ull; }

    #pragma unroll 8
    for (int k = 0; k < 128; k++) {
        float4 bv = *(const float4*)&Wsm[k * 128 + cg * 4];
        unsigned long long b01, b23;
        asm("mov.b64 %0, {%1,%2};" : "=l"(b01) : "f"(bv.x), "f"(bv.y));
        asm("mov.b64 %0, {%1,%2};" : "=l"(b23) : "f"(bv.z), "f"(bv.w));
        const float4* zp4 = (const float4*)&Zsm[k * ZPAD + rg * 8];
        float4 za = zp4[0];
        float4 zb = zp4[1];
        float av[8] = {za.x, za.y, za.z, za.w, zb.x, zb.y, zb.z, zb.w};
        #pragma unroll
        for (int i = 0; i < 8; i++) {
            unsigned long long aa;
            asm("mov.b64 %0, {%1,%1};" : "=l"(aa) : "f"(av[i]));
            asm("fma.rn.f32x2 %0, %1, %2, %0;" : "+l"(acc[i][0]) : "l"(aa), "l"(b01));
            asm("fma.rn.f32x2 %0, %1, %2, %0;" : "+l"(acc[i][1]) : "l"(aa), "l"(b23));
        }
    }

    #pragma unroll
    for (int i = 0; i < 8; i++) {
        int row = row0 + rg * 8 + i;
        if (row < N_NODES) {
            float4 o;
            asm("mov.b64 {%0,%1}, %2;" : "=f"(o.x), "=f"(o.y) : "l"(acc[i][0]));
            asm("mov.b64 {%0,%1}, %2;" : "=f"(o.z), "=f"(o.w) : "l"(acc[i][1]));
            ((float4*)H)[(size_t)row * 32 + cg] = o;
        }
    }
}

// ---------------- Aggregation + bias + ReLU + BN-stat accumulation ----------
// one warp per dst row (grid-stride); lane owns cols lane*4..lane*4+3
__global__ void __launch_bounds__(256) agg_kernel(const float* __restrict__ bvec) {
    __shared__ float red[8 * 256];

    int lane = threadIdx.x & 31;
    int wid  = threadIdx.x >> 5;
    int gw   = blockIdx.x * 8 + wid;
    int nw   = gridDim.x * 8;

    float4 bb = ((const float4*)bvec)[lane];

    float s0 = 0.f, s1 = 0.f, s2 = 0.f, s3 = 0.f;
    float q0 = 0.f, q1 = 0.f, q2 = 0.f, q3 = 0.f;

    const float4* h4 = (const float4*)g_h;

    for (int r = gw; r < N_NODES; r += nw) {
        float dr = g_dis[r];
        float4 hv = h4[(size_t)r * 32 + lane];
        float cself = dr * dr;
        float4 acc;
        acc.x = hv.x * cself; acc.y = hv.y * cself;
        acc.z = hv.z * cself; acc.w = hv.w * cself;

        int beg = g_rowptr[r], end = g_rowptr[r + 1];
        for (int j = beg; j < end; j++) {
            int2 e = __ldg(&g_edge[j]);
            float c = __int_as_float(e.y);
            float4 hs = h4[(size_t)e.x * 32 + lane];
            acc.x = fmaf(c, hs.x, acc.x);
            acc.y = fmaf(c, hs.y, acc.y);
            acc.z = fmaf(c, hs.z, acc.z);
            acc.w = fmaf(c, hs.w, acc.w);
        }
        acc.x = fmaxf(acc.x + bb.x, 0.f);
        acc.y = fmaxf(acc.y + bb.y, 0.f);
        acc.z = fmaxf(acc.z + bb.z, 0.f);
        acc.w = fmaxf(acc.w + bb.w, 0.f);
        ((float4*)g_y)[(size_t)r * 32 + lane] = acc;

        s0 += acc.x; s1 += acc.y; s2 += acc.z; s3 += acc.w;
        q0 = fmaf(acc.x, acc.x, q0); q1 = fmaf(acc.y, acc.y, q1);
        q2 = fmaf(acc.z, acc.z, q2); q3 = fmaf(acc.w, acc.w, q3);
    }

    float* rw = &red[wid * 256 + lane * 8];
    rw[0] = s0; rw[1] = s1; rw[2] = s2; rw[3] = s3;
    rw[4] = q0; rw[5] = q1; rw[6] = q2; rw[7] = q3;
    __syncthreads();

    int tid = threadIdx.x;
    float a = 0.f;
    #pragma unroll
    for (int w = 0; w < 8; w++) a += red[w * 256 + tid];
    int l = tid >> 3, j = tid & 7;
    int col = l * 4 + (j & 3);
    atomicAdd(&g_stats[(j >> 2) * 128 + col], (double)a);
}

// ---------------- BN finalize (self-zeroing stats) ---------------------------
__global__ void stats_kernel(const float* __restrict__ gamma,
                             const float* __restrict__ beta) {
    int c = threadIdx.x;
    double s = g_stats[c];
    double q = g_stats[128 + c];
    g_stats[c] = 0.0;
    g_stats[128 + c] = 0.0;
    double mu  = s * (1.0 / N_NODES);
    double var = q * (1.0 / N_NODES) - mu * mu;
    float scale = gamma[c] * rsqrtf((float)var + BN_EPS);
    g_affine[c]       = scale;
    g_affine[128 + c] = beta[c] - (float)mu * scale;
}

// ---------------- final normalize (elementwise affine, last layer only) ------
__global__ void __launch_bounds__(256) norm_kernel(float* __restrict__ out) {
    int idx = blockIdx.x * blockDim.x + threadIdx.x;  // float4 index
    if (idx < N_NODES * 32) {
        int c4 = idx & 31;
        float4 v  = ((const float4*)g_y)[idx];
        float4 sc = ((const float4*)g_affine)[c4];
        float4 sh = ((const float4*)(g_affine + 128))[c4];
        v.x = fmaf(v.x, sc.x, sh.x);
        v.y = fmaf(v.y, sc.y, sh.y);
        v.z = fmaf(v.z, sc.z, sh.z);
        v.w = fmaf(v.w, sc.w, sh.w);
        ((float4*)out)[idx] = v;
    }
}

// ---------------- launch -----------------------------------------------------
extern "C" void kernel_launch(void* const* d_in, const int* in_sizes, int n_in,
                              void* d_out, int out_size) {
    const float* x      = (const float*)d_in[0];
    const int*   ei     = (const int*)d_in[1];
    const float* Ws     = (const float*)d_in[2];
    const float* bs     = (const float*)d_in[3];
    const float* gammas = (const float*)d_in[4];
    const float* betas  = (const float*)d_in[5];
    const int* src = ei;
    const int* dst = ei + N_EDGES;

    void *p_h, *p_y;
    cudaGetSymbolAddress(&p_h, g_h);
    cudaGetSymbolAddress(&p_y, g_y);

    cudaFuncSetAttribute(gemm_kernel, cudaFuncAttributeMaxDynamicSharedMemorySize,
                         GEMM_SMEM_BYTES);

    // CSR build (edge structure is layer-invariant; g_deg self-zeroed by scan)
    count_kernel<<<(N_EDGES + 255) / 256, 256>>>(dst);
    scan_kernel<<<1, 1024>>>();
    scatter_kernel<<<(N_EDGES + 255) / 256, 256>>>(src, dst);

    const float* zin = x;
    for (int l = 0; l < N_LAYERS; l++) {
        gemm_kernel<<<(N_NODES + 63) / 64, 256, GEMM_SMEM_BYTES>>>(
            zin, Ws + (size_t)l * DIM * DIM, (float*)p_h, l > 0 ? 1 : 0);
        agg_kernel<<<1024, 256>>>(bs + l * DIM);
        stats_kernel<<<1, 128>>>(gammas + l * DIM, betas + l * DIM);
        zin = (const float*)p_y;   // next GEMM applies BN affine while loading
    }
    norm_kernel<<<(N_NODES * 32 + 255) / 256, 256>>>((float*)d_out);
}